// round 10
// baseline (speedup 1.0000x reference)
#include <cuda_runtime.h>
#include <cstdint>

// ---------------------------------------------------------------------------
// Problem constants
// ---------------------------------------------------------------------------
#define B 64
#define N 2048
#define DIM 768
#define POOL 1024
#define LEN 16
#define NOUT 2080                 // 2*LEN + N
#define C4 (DIM / 4)              // 192 float4 per row
#define NCHUNK 32
#define TOKPC (N / NCHUNK)        // 64
#define SCALAR_OFF ((size_t)B * NOUT * DIM)
#define KSTRIPE (DIM / 8)         // 96 k's per warp in sim
#define GRID_T 148                // tail kernel grid (1 block/SM, co-resident)

// ---------------------------------------------------------------------------
// Device scratch (no allocations). Only touched from device code — passing
// these symbols from host binds the host shadow copy (ATS trap).
// ---------------------------------------------------------------------------
__device__ __align__(16) float4 g_part[B * NCHUNK * C4];  // per-(b,chunk) sums
__device__ __align__(16) float  g_xnormT[DIM * B];        // x_norm^T [c][b]
__device__ __align__(16) float  g_residT[DIM * B];        // residual^T [c][b]
__device__ __align__(16) float  g_sim[B * POOL];          // sim [b][p]
__device__ __align__(16) float  g_rsim[B * POOL];         // res-sim [b][p]
__device__ int    g_idx1[B];
__device__ int    g_idx2[B];
__device__ float  g_best1[B];
__device__ float  g_best2[B];

// software grid barrier state (persistent across launches/replays: count
// always returns to 0; phase is monotonically increasing — both fine).
__device__ volatile unsigned g_bar_phase;
__device__ unsigned          g_bar_count;

// ---------------------------------------------------------------------------
// 1) Fused: copy x_embed -> out rows [32,2080) AND per-(b,chunk,c) sums.
//    grid = B*32 = 2048, block = 192. Deterministic (no atomics).
// ---------------------------------------------------------------------------
__global__ __launch_bounds__(C4) void copy_mean_kernel(
    const float4* __restrict__ x, float4* __restrict__ out4)
{
    int b     = blockIdx.x >> 5;
    int chunk = blockIdx.x & 31;
    int c4    = threadIdx.x;                         // 0..191

    size_t xbase = ((size_t)b * N + (size_t)chunk * TOKPC) * C4 + c4;
    size_t obase = ((size_t)b * NOUT + 2 * LEN + (size_t)chunk * TOKPC) * C4 + c4;

    float ax = 0.f, ay = 0.f, az = 0.f, aw = 0.f;
#pragma unroll 8
    for (int t = 0; t < TOKPC; ++t) {
        float4 v = x[xbase + (size_t)t * C4];
        out4[obase + (size_t)t * C4] = v;
        ax += v.x; ay += v.y; az += v.z; aw += v.w;
    }
    g_part[(b * NCHUNK + chunk) * C4 + c4] = make_float4(ax, ay, az, aw);
}

// ---------------------------------------------------------------------------
// grid barrier: all GRID_T blocks are co-resident by construction
// (148 blocks, 256 thr, <6KB smem, <64 regs -> >=1 block per SM).
// Classic threadfence arrive/spin pattern; deterministic.
// ---------------------------------------------------------------------------
__device__ __forceinline__ void grid_barrier()
{
    __threadfence();
    __syncthreads();
    if (threadIdx.x == 0) {
        unsigned gen = g_bar_phase;            // read BEFORE arriving
        unsigned old = atomicAdd(&g_bar_count, 1u);
        if (old == GRID_T - 1) {
            g_bar_count = 0;
            __threadfence();
            g_bar_phase = gen + 1;
        } else {
            while (g_bar_phase == gen) __nanosleep(64);
        }
    }
    __syncthreads();
}

// ---------------------------------------------------------------------------
// sim phase body: sim[b][p] for one pool-row pair p0, key norms inline.
// 8 warps split k; lane owns a batch pair. Caller provides smem.
// ---------------------------------------------------------------------------
__device__ __forceinline__ void sim_pair(
    const float* __restrict__ keys, const float* __restrict__ vecT,
    float* __restrict__ simB, int p0,
    float4 (*spart)[32], float2* snorm)
{
    int warp = threadIdx.x >> 5, lane = threadIdx.x & 31;
    const float*  k0p = keys + (size_t)p0 * DIM;
    const float*  k1p = k0p + DIM;
    const float2* xv  = (const float2*)vecT + lane;    // +k*(B/2)

    float a0x = 0.f, a0y = 0.f, a1x = 0.f, a1y = 0.f;
    float ss0 = 0.f, ss1 = 0.f;
    int kb = warp * KSTRIPE;
#pragma unroll 8
    for (int i = 0; i < KSTRIPE; ++i) {
        int k = kb + i;
        float  kv0 = __ldg(k0p + k);
        float  kv1 = __ldg(k1p + k);
        ss0 += kv0 * kv0;
        ss1 += kv1 * kv1;
        float2 x = xv[(size_t)k * (B / 2)];
        a0x += kv0 * x.x; a0y += kv0 * x.y;
        a1x += kv1 * x.x; a1y += kv1 * x.y;
    }
    spart[warp][lane] = make_float4(a0x, a0y, a1x, a1y);
    if (lane == 0) snorm[warp] = make_float2(ss0, ss1);
    __syncthreads();
    if (warp == 0) {
        float sx = 0.f, sy = 0.f, tx = 0.f, ty = 0.f;
        float n0 = 0.f, n1 = 0.f;
#pragma unroll
        for (int w = 0; w < 8; ++w) {
            float4 v = spart[w][lane];
            sx += v.x; sy += v.y; tx += v.z; ty += v.w;
            n0 += snorm[w].x; n1 += snorm[w].y;
        }
        float i0 = rsqrtf(fmaxf(n0, 1e-12f));
        float i1 = rsqrtf(fmaxf(n1, 1e-12f));
        int b0 = lane * 2;
        simB[(size_t)b0 * POOL + p0]           = sx * i0;
        simB[(size_t)(b0 + 1) * POOL + p0]     = sy * i0;
        simB[(size_t)b0 * POOL + p0 + 1]       = tx * i1;
        simB[(size_t)(b0 + 1) * POOL + p0 + 1] = ty * i1;
    }
    __syncthreads();
}

// ---------------------------------------------------------------------------
// argmax phase body for batch b (lowest index wins ties). Returns idx via
// smem; writes g_idx/g_best. STAGE 0 also builds residT.
// ---------------------------------------------------------------------------
template <int STAGE>
__device__ __forceinline__ void argmax_body(
    const float* __restrict__ pk, int b,
    float* swv, int* swi, int* s_idx)
{
    int tid = threadIdx.x;
    int warp = tid >> 5, lane = tid & 31;
    const float* simRow = (STAGE ? g_rsim : g_sim) + (size_t)b * POOL;
    float4 v4 = ((const float4*)simRow)[tid];

    float best = v4.x; int bi = tid * 4;
    if (v4.y > best) { best = v4.y; bi = tid * 4 + 1; }
    if (v4.z > best) { best = v4.z; bi = tid * 4 + 2; }
    if (v4.w > best) { best = v4.w; bi = tid * 4 + 3; }

#pragma unroll
    for (int o = 16; o > 0; o >>= 1) {
        float vo = __shfl_down_sync(0xffffffffu, best, o);
        int   io = __shfl_down_sync(0xffffffffu, bi, o);
        if (vo > best || (vo == best && io < bi)) { best = vo; bi = io; }
    }
    if (lane == 0) { swv[warp] = best; swi[warp] = bi; }
    __syncthreads();
    if (tid == 0) {
        float v = swv[0]; int id = swi[0];
#pragma unroll
        for (int w = 1; w < 8; ++w) {
            if (swv[w] > v || (swv[w] == v && swi[w] < id)) {
                v = swv[w]; id = swi[w];
            }
        }
        *s_idx = id;
        if (STAGE) { g_idx2[b] = id; g_best2[b] = v; }
        else       { g_idx1[b] = id; g_best1[b] = v; }
    }
    __syncthreads();
    if (!STAGE) {
        int idx = *s_idx;
#pragma unroll
        for (int i = 0; i < 3; ++i) {
            int c = tid + i * 256;
            g_residT[c * B + b] = pk[(size_t)idx * DIM + c] - g_xnormT[c * B + b];
        }
    }
    __syncthreads();
}

// ---------------------------------------------------------------------------
// 2) ONE resident tail kernel: xnorm -> sim0 -> argmax0 -> sim1 -> argmax1
//    -> gathers+scalar, separated by software grid barriers.
//    grid = GRID_T = 148, block = 256.
// ---------------------------------------------------------------------------
__global__ __launch_bounds__(256) void tail_kernel(
    const float* __restrict__ pkey,
    const float* __restrict__ rpkey,
    const float4* __restrict__ prompt4,
    const float4* __restrict__ rprompt4,
    float4* __restrict__ out4,
    float* __restrict__ out_scalar,
    int write_scalar)
{
    __shared__ float4 spart[8][32];
    __shared__ float2 snorm[8];
    __shared__ float  swv[8];
    __shared__ int    swi[8];
    __shared__ int    s_idx;

    int tid = threadIdx.x;
    int warp = tid >> 5, lane = tid & 31;

    // ---- Phase A: x_norm (blocks 0..63) ----
    if (blockIdx.x < B) {
        int b = blockIdx.x;
        int c4 = tid;
        float sx = 0.f, sy = 0.f, sz = 0.f, sw = 0.f;
        if (c4 < C4) {
#pragma unroll
            for (int k = 0; k < NCHUNK; ++k) {
                float4 p = g_part[(b * NCHUNK + k) * C4 + c4];
                sx += p.x; sy += p.y; sz += p.z; sw += p.w;
            }
            const float invN = 1.0f / (float)N;
            sx *= invN; sy *= invN; sz *= invN; sw *= invN;
        }
        float ss = sx * sx + sy * sy + sz * sz + sw * sw;
#pragma unroll
        for (int o = 16; o > 0; o >>= 1)
            ss += __shfl_down_sync(0xffffffffu, ss, o);
        if (lane == 0) swv[warp] = ss;
        __syncthreads();
        if (tid == 0) {
            float tot = 0.f;
#pragma unroll
            for (int w = 0; w < 8; ++w) tot += swv[w];
            swv[0] = rsqrtf(fmaxf(tot, 1e-12f));
        }
        __syncthreads();
        if (c4 < C4) {
            float inv = swv[0];
            int c = c4 * 4;
            g_xnormT[(c + 0) * B + b] = sx * inv;
            g_xnormT[(c + 1) * B + b] = sy * inv;
            g_xnormT[(c + 2) * B + b] = sz * inv;
            g_xnormT[(c + 3) * B + b] = sw * inv;
        }
    }
    grid_barrier();

    // ---- Phase B: sim0 (grid-strided over 512 pool-row pairs) ----
    for (int pp = blockIdx.x; pp < POOL / 2; pp += GRID_T)
        sim_pair(pkey, g_xnormT, g_sim, pp * 2, spart, snorm);
    grid_barrier();

    // ---- Phase C: argmax0 + residual (blocks 0..63) ----
    if (blockIdx.x < B)
        argmax_body<0>(pkey, blockIdx.x, swv, swi, &s_idx);
    grid_barrier();

    // ---- Phase D: sim1 ----
    for (int pp = blockIdx.x; pp < POOL / 2; pp += GRID_T)
        sim_pair(rpkey, g_residT, g_rsim, pp * 2, spart, snorm);
    grid_barrier();

    // ---- Phase E: argmax1 (blocks 0..63) ----
    if (blockIdx.x < B)
        argmax_body<1>(nullptr, blockIdx.x, swv, swi, &s_idx);
    grid_barrier();

    // ---- Phase F: gathers (grid-strided) + scalar (block 0) ----
    if (blockIdx.x == 0 && write_scalar) {
        if (tid < 64) {
            float v = g_best1[tid] + g_best2[tid];
#pragma unroll
            for (int o = 16; o > 0; o >>= 1)
                v += __shfl_down_sync(0xffffffffu, v, o);
            if ((tid & 31) == 0) swv[tid >> 5] = v;
        }
        __syncthreads();
        if (tid == 0)
            out_scalar[SCALAR_OFF] = (swv[0] + swv[1]) * (1.0f / (float)B);
    }
    const int HQ = (LEN / 2) * C4;                   // 1536 float4 per half
    for (int w = blockIdx.x; w < 4 * B; w += GRID_T) {
        int b     = w >> 2;
        int which = (w >> 1) & 1;
        int half  = w & 1;
        int idx = which ? g_idx1[b] : g_idx2[b];
        const float4* src = (which ? prompt4 : rprompt4)
                            + (size_t)idx * LEN * C4 + (size_t)half * HQ;
        float4* dst = out4 + ((size_t)b * NOUT + (which ? LEN : 0)
                              + (size_t)half * (LEN / 2)) * C4;
#pragma unroll
        for (int i = 0; i < HQ / 256; ++i)
            dst[tid + i * 256] = src[tid + i * 256];
    }
}

// ---------------------------------------------------------------------------
// launch
// ---------------------------------------------------------------------------
extern "C" void kernel_launch(void* const* d_in, const int* in_sizes, int n_in,
                              void* d_out, int out_size)
{
    // Map inputs by element count (order-robust).
    const float* x_embed = nullptr;
    const float* prompt = nullptr, * rprompt = nullptr;
    const float* pkey = nullptr, * rpkey = nullptr;
    for (int i = 0; i < n_in; ++i) {
        int sz = in_sizes[i];
        if (sz == B * N * DIM) x_embed = (const float*)d_in[i];
        else if (sz == POOL * LEN * DIM) {
            if (!prompt) prompt = (const float*)d_in[i];
            else if (!rprompt) rprompt = (const float*)d_in[i];
        } else if (sz == POOL * DIM) {
            if (!pkey) pkey = (const float*)d_in[i];
            else if (!rpkey) rpkey = (const float*)d_in[i];
        }
    }
    float* out = (float*)d_out;

    copy_mean_kernel<<<B * NCHUNK, C4>>>((const float4*)x_embed, (float4*)out);
    int write_scalar = ((size_t)out_size > SCALAR_OFF) ? 1 : 0;
    tail_kernel<<<GRID_T, 256>>>(pkey, rpkey,
                                 (const float4*)prompt, (const float4*)rprompt,
                                 (float4*)out, out, write_scalar);
}

// round 11
// speedup vs baseline: 1.3718x; 1.3718x over previous
#include <cuda_runtime.h>
#include <cstdint>

// ---------------------------------------------------------------------------
// Problem constants
// ---------------------------------------------------------------------------
#define B 64
#define N 2048
#define DIM 768
#define POOL 1024
#define LEN 16
#define NOUT 2080                 // 2*LEN + N
#define C4 (DIM / 4)              // 192 float4 per row
#define NCHUNK 32
#define TOKPC (N / NCHUNK)        // 64
#define SCALAR_OFF ((size_t)B * NOUT * DIM)
#define KSTRIPE (DIM / 8)         // 96 k's per warp in sim

// ---------------------------------------------------------------------------
// Device scratch (no allocations). Only touched from device code — passing
// these symbols from host binds the host shadow copy (ATS trap).
// ---------------------------------------------------------------------------
__device__ __align__(16) float4 g_part[B * NCHUNK * C4];  // per-(b,chunk) sums
__device__ __align__(16) float  g_xnormT[DIM * B];        // x_norm^T [c][b]
__device__ __align__(16) float  g_residT[DIM * B];        // residual^T [c][b]
__device__ unsigned long long   g_pack1[B];  // (flip(best)<<32)|~idx, stage 0
__device__ unsigned long long   g_pack2[B];  // stage 1

// ---------------------------------------------------------------------------
// order-monotonic float<->u32 mapping + pack/unpack helpers
// max(pack) == max value, ties -> lowest pool index (low word = ~idx).
// ---------------------------------------------------------------------------
__device__ __forceinline__ unsigned flip_f(float v) {
    unsigned b = __float_as_uint(v);
    return b ^ ((b & 0x80000000u) ? 0xffffffffu : 0x80000000u);
}
__device__ __forceinline__ float unflip_f(unsigned k) {
    unsigned b = k ^ ((k & 0x80000000u) ? 0x80000000u : 0xffffffffu);
    return __uint_as_float(b);
}
__device__ __forceinline__ unsigned long long pack_vi(float v, int idx) {
    return ((unsigned long long)flip_f(v) << 32) |
           (unsigned long long)(0xffffffffu - (unsigned)idx);
}
__device__ __forceinline__ int unpack_idx(unsigned long long p) {
    return (int)(0xffffffffu - (unsigned)(p & 0xffffffffu));
}
__device__ __forceinline__ float unpack_val(unsigned long long p) {
    return unflip_f((unsigned)(p >> 32));
}

// ---------------------------------------------------------------------------
// 1) Fused: copy x_embed -> out rows [32,2080) AND per-(b,chunk,c) sums.
//    grid = B*32 = 2048, block = 192. Streaming hints: touched-once data.
// ---------------------------------------------------------------------------
__global__ __launch_bounds__(C4) void copy_mean_kernel(
    const float4* __restrict__ x, float4* __restrict__ out4)
{
    int b     = blockIdx.x >> 5;
    int chunk = blockIdx.x & 31;
    int c4    = threadIdx.x;                         // 0..191

    size_t xbase = ((size_t)b * N + (size_t)chunk * TOKPC) * C4 + c4;
    size_t obase = ((size_t)b * NOUT + 2 * LEN + (size_t)chunk * TOKPC) * C4 + c4;

    float ax = 0.f, ay = 0.f, az = 0.f, aw = 0.f;
#pragma unroll 8
    for (int t = 0; t < TOKPC; ++t) {
        float4 v = __ldcs(x + xbase + (size_t)t * C4);
        __stcs(out4 + obase + (size_t)t * C4, v);
        ax += v.x; ay += v.y; az += v.z; aw += v.w;
    }
    g_part[(b * NCHUNK + chunk) * C4 + c4] = make_float4(ax, ay, az, aw);
}

// ---------------------------------------------------------------------------
// 2) x_norm = l2norm(mean) -> g_xnormT (transposed); also re-arms the
//    per-batch atomic-max cells for this replay.  grid=B, block=256.
// ---------------------------------------------------------------------------
__global__ __launch_bounds__(256) void xnorm_kernel()
{
    __shared__ float sh[8];
    int tid = threadIdx.x;
    int warp = tid >> 5, lane = tid & 31;
    int b = blockIdx.x;
    if (tid == 0) { g_pack1[b] = 0ull; g_pack2[b] = 0ull; }
    int c4 = tid;
    float sx = 0.f, sy = 0.f, sz = 0.f, sw = 0.f;
    if (c4 < C4) {
#pragma unroll
        for (int k = 0; k < NCHUNK; ++k) {
            float4 p = g_part[(b * NCHUNK + k) * C4 + c4];
            sx += p.x; sy += p.y; sz += p.z; sw += p.w;
        }
        const float invN = 1.0f / (float)N;
        sx *= invN; sy *= invN; sz *= invN; sw *= invN;
    }
    float ss = sx * sx + sy * sy + sz * sz + sw * sw;
#pragma unroll
    for (int o = 16; o > 0; o >>= 1) ss += __shfl_down_sync(0xffffffffu, ss, o);
    if (lane == 0) sh[warp] = ss;
    __syncthreads();
    if (tid == 0) {
        float tot = 0.f;
#pragma unroll
        for (int w = 0; w < 8; ++w) tot += sh[w];
        sh[0] = rsqrtf(fmaxf(tot, 1e-12f));
    }
    __syncthreads();
    if (c4 < C4) {
        float inv = sh[0];
        int c = c4 * 4;
        g_xnormT[(c + 0) * B + b] = sx * inv;
        g_xnormT[(c + 1) * B + b] = sy * inv;
        g_xnormT[(c + 2) * B + b] = sz * inv;
        g_xnormT[(c + 3) * B + b] = sw * inv;
    }
}

// ---------------------------------------------------------------------------
// 3) sim + fused argmax: block handles pool rows (p0, p0+1); 8 warps split k;
//    lane owns a batch pair; key norms inline. Warp 0 folds the 2 rows to a
//    per-batch best and RED.MAX-packs it into g_pack (order-independent).
//    grid = POOL/2 = 512, block = 256.
// ---------------------------------------------------------------------------
template <int STAGE>
__global__ __launch_bounds__(256) void sim_kernel(const float* __restrict__ keys)
{
    const float* vecT = STAGE ? g_residT : g_xnormT;   // [DIM][B]
    unsigned long long* packs = STAGE ? g_pack2 : g_pack1;

    int p0   = blockIdx.x * 2;
    int warp = threadIdx.x >> 5, lane = threadIdx.x & 31;

    const float*  k0p = keys + (size_t)p0 * DIM;
    const float*  k1p = k0p + DIM;
    const float2* xv  = (const float2*)vecT + lane;    // +k*(B/2)

    float a0x = 0.f, a0y = 0.f, a1x = 0.f, a1y = 0.f;
    float ss0 = 0.f, ss1 = 0.f;                        // identical across lanes
    int kb = warp * KSTRIPE;
#pragma unroll 8
    for (int i = 0; i < KSTRIPE; ++i) {
        int k = kb + i;
        float  kv0 = __ldg(k0p + k);
        float  kv1 = __ldg(k1p + k);
        ss0 += kv0 * kv0;
        ss1 += kv1 * kv1;
        float2 x = xv[(size_t)k * (B / 2)];
        a0x += kv0 * x.x; a0y += kv0 * x.y;
        a1x += kv1 * x.x; a1y += kv1 * x.y;
    }
    __shared__ float4 spart[8][32];
    __shared__ float2 snorm[8];
    spart[warp][lane] = make_float4(a0x, a0y, a1x, a1y);
    if (lane == 0) snorm[warp] = make_float2(ss0, ss1);
    __syncthreads();
    if (warp == 0) {
        float sx = 0.f, sy = 0.f, tx = 0.f, ty = 0.f;
        float n0 = 0.f, n1 = 0.f;
#pragma unroll
        for (int w = 0; w < 8; ++w) {
            float4 v = spart[w][lane];
            sx += v.x; sy += v.y; tx += v.z; ty += v.w;
            n0 += snorm[w].x; n1 += snorm[w].y;
        }
        float i0 = rsqrtf(fmaxf(n0, 1e-12f));
        float i1 = rsqrtf(fmaxf(n1, 1e-12f));
        // batch b0 = 2*lane: rows p0 (sx*i0) and p0+1 (tx*i1)
        float v0a = sx * i0, v0b = tx * i1;
        float v1a = sy * i0, v1b = ty * i1;
        int b0 = lane * 2;
        // fold 2 rows (strict > keeps lower p on ties), then one RED each
        float bv0 = v0a; int bp0 = p0;
        if (v0b > bv0) { bv0 = v0b; bp0 = p0 + 1; }
        float bv1 = v1a; int bp1 = p0;
        if (v1b > bv1) { bv1 = v1b; bp1 = p0 + 1; }
        atomicMax(&packs[b0],     pack_vi(bv0, bp0));
        atomicMax(&packs[b0 + 1], pack_vi(bv1, bp1));
    }
}

// ---------------------------------------------------------------------------
// 4) resid: residT[c][b] = pk[idx1[b]][c] - xnormT[c][b].  grid=B, block=256.
// ---------------------------------------------------------------------------
__global__ __launch_bounds__(256) void resid_kernel(const float* __restrict__ pk)
{
    int b = blockIdx.x, tid = threadIdx.x;
    int idx = unpack_idx(g_pack1[b]);
#pragma unroll
    for (int i = 0; i < 3; ++i) {
        int c = tid + i * 256;
        g_residT[c * B + b] = pk[(size_t)idx * DIM + c] - g_xnormT[c * B + b];
    }
}

// ---------------------------------------------------------------------------
// 5) finish: both gathers spread over 256 blocks + scalar in block 256.
//    which=0 -> residual_prompt[idx2] @ out rows [0,16)
//    which=1 -> prompt[idx1]          @ out rows [16,32)
// ---------------------------------------------------------------------------
__global__ __launch_bounds__(256) void finish_kernel(
    const float4* __restrict__ prompt4,
    const float4* __restrict__ rprompt4,
    float4* __restrict__ out4,
    float* __restrict__ out_scalar,
    int write_scalar)
{
    if (blockIdx.x == 4 * B) {
        __shared__ float sh[2];
        if (write_scalar && threadIdx.x < 64) {
            float v = unpack_val(g_pack1[threadIdx.x]) +
                      unpack_val(g_pack2[threadIdx.x]);
#pragma unroll
            for (int o = 16; o > 0; o >>= 1)
                v += __shfl_down_sync(0xffffffffu, v, o);
            if ((threadIdx.x & 31) == 0) sh[threadIdx.x >> 5] = v;
        }
        __syncthreads();
        if (write_scalar && threadIdx.x == 0)
            out_scalar[SCALAR_OFF] = (sh[0] + sh[1]) * (1.0f / (float)B);
        return;
    }
    int b     = blockIdx.x >> 2;
    int which = (blockIdx.x >> 1) & 1;
    int half  = blockIdx.x & 1;
    int idx = which ? unpack_idx(g_pack1[b]) : unpack_idx(g_pack2[b]);
    const int HQ = (LEN / 2) * C4;                   // 1536 float4 per half
    const float4* src = (which ? prompt4 : rprompt4)
                        + (size_t)idx * LEN * C4 + (size_t)half * HQ;
    float4* dst = out4 + ((size_t)b * NOUT + (which ? LEN : 0)
                          + (size_t)half * (LEN / 2)) * C4;
#pragma unroll
    for (int i = 0; i < HQ / 256; ++i)
        dst[threadIdx.x + i * 256] = src[threadIdx.x + i * 256];
}

// ---------------------------------------------------------------------------
// launch
// ---------------------------------------------------------------------------
extern "C" void kernel_launch(void* const* d_in, const int* in_sizes, int n_in,
                              void* d_out, int out_size)
{
    // Map inputs by element count (order-robust).
    const float* x_embed = nullptr;
    const float* prompt = nullptr, * rprompt = nullptr;
    const float* pkey = nullptr, * rpkey = nullptr;
    for (int i = 0; i < n_in; ++i) {
        int sz = in_sizes[i];
        if (sz == B * N * DIM) x_embed = (const float*)d_in[i];
        else if (sz == POOL * LEN * DIM) {
            if (!prompt) prompt = (const float*)d_in[i];
            else if (!rprompt) rprompt = (const float*)d_in[i];
        } else if (sz == POOL * DIM) {
            if (!pkey) pkey = (const float*)d_in[i];
            else if (!rpkey) rpkey = (const float*)d_in[i];
        }
    }
    float* out = (float*)d_out;

    copy_mean_kernel<<<B * NCHUNK, C4>>>((const float4*)x_embed, (float4*)out);
    xnorm_kernel<<<B, 256>>>();
    sim_kernel<0><<<POOL / 2, 256>>>(pkey);
    resid_kernel<<<B, 256>>>(pkey);
    sim_kernel<1><<<POOL / 2, 256>>>(rpkey);
    int write_scalar = ((size_t)out_size > SCALAR_OFF) ? 1 : 0;
    finish_kernel<<<4 * B + 1, 256>>>(
        (const float4*)prompt, (const float4*)rprompt, (float4*)out,
        out, write_scalar);
}

// round 12
// speedup vs baseline: 1.5066x; 1.0983x over previous
#include <cuda_runtime.h>
#include <cstdint>

// ---------------------------------------------------------------------------
// Problem constants
// ---------------------------------------------------------------------------
#define B 64
#define N 2048
#define DIM 768
#define POOL 1024
#define LEN 16
#define NOUT 2080                 // 2*LEN + N
#define C4 (DIM / 4)              // 192 float4 per row
#define NCHUNK 32
#define TOKPC (N / NCHUNK)        // 64
#define SCALAR_OFF ((size_t)B * NOUT * DIM)
#define KSTRIPE (DIM / 8)         // 96 k's per warp in sim

// ---------------------------------------------------------------------------
// Device scratch (no allocations). Only touched from device code — passing
// these symbols from host binds the host shadow copy (ATS trap).
// ---------------------------------------------------------------------------
__device__ __align__(16) float4 g_part[B * NCHUNK * C4];  // per-(b,chunk) sums
__device__ __align__(16) float  g_xnormT[DIM * B];        // x_norm^T [c][b]
__device__ __align__(16) float  g_residT[DIM * B];        // residual^T [c][b]
__device__ __align__(16) float  g_sim[B * POOL];          // sim [b][p]
__device__ __align__(16) float  g_rsim[B * POOL];         // res-sim [b][p]
__device__ int    g_idx1[B];
__device__ int    g_idx2[B];
__device__ float  g_best1[B];
__device__ float  g_best2[B];

// ---------------------------------------------------------------------------
// 1) Fused: copy x_embed -> out rows [32,2080) AND per-(b,chunk,c) sums.
//    grid = B*32 = 2048, block = 192. (Byte-identical to R9 best.)
// ---------------------------------------------------------------------------
__global__ __launch_bounds__(C4) void copy_mean_kernel(
    const float4* __restrict__ x, float4* __restrict__ out4)
{
    int b     = blockIdx.x >> 5;
    int chunk = blockIdx.x & 31;
    int c4    = threadIdx.x;                         // 0..191

    size_t xbase = ((size_t)b * N + (size_t)chunk * TOKPC) * C4 + c4;
    size_t obase = ((size_t)b * NOUT + 2 * LEN + (size_t)chunk * TOKPC) * C4 + c4;

    float ax = 0.f, ay = 0.f, az = 0.f, aw = 0.f;
#pragma unroll 8
    for (int t = 0; t < TOKPC; ++t) {
        float4 v = x[xbase + (size_t)t * C4];
        out4[obase + (size_t)t * C4] = v;
        ax += v.x; ay += v.y; az += v.z; aw += v.w;
    }
    g_part[(b * NCHUNK + chunk) * C4 + c4] = make_float4(ax, ay, az, aw);
}

// ---------------------------------------------------------------------------
// 2) x_norm = l2norm(mean) -> g_xnormT (transposed).  grid=B, block=256. PDL.
// ---------------------------------------------------------------------------
__global__ __launch_bounds__(256) void xnorm_kernel()
{
    cudaGridDependencySynchronize();
    __shared__ float sh[8];
    int tid = threadIdx.x;
    int warp = tid >> 5, lane = tid & 31;
    int b = blockIdx.x;
    int c4 = tid;
    float sx = 0.f, sy = 0.f, sz = 0.f, sw = 0.f;
    if (c4 < C4) {
#pragma unroll
        for (int k = 0; k < NCHUNK; ++k) {
            float4 p = g_part[(b * NCHUNK + k) * C4 + c4];
            sx += p.x; sy += p.y; sz += p.z; sw += p.w;
        }
        const float invN = 1.0f / (float)N;
        sx *= invN; sy *= invN; sz *= invN; sw *= invN;
    }
    float ss = sx * sx + sy * sy + sz * sz + sw * sw;
#pragma unroll
    for (int o = 16; o > 0; o >>= 1) ss += __shfl_down_sync(0xffffffffu, ss, o);
    if (lane == 0) sh[warp] = ss;
    __syncthreads();
    if (tid == 0) {
        float tot = 0.f;
#pragma unroll
        for (int w = 0; w < 8; ++w) tot += sh[w];
        sh[0] = rsqrtf(fmaxf(tot, 1e-12f));
    }
    __syncthreads();
    if (c4 < C4) {
        float inv = sh[0];
        int c = c4 * 4;
        g_xnormT[(c + 0) * B + b] = sx * inv;
        g_xnormT[(c + 1) * B + b] = sy * inv;
        g_xnormT[(c + 2) * B + b] = sz * inv;
        g_xnormT[(c + 3) * B + b] = sw * inv;
    }
}

// ---------------------------------------------------------------------------
// 3) sim[b][p] = dot(vec[b], key[p]) * rsqrt(max(||key[p]||^2, eps))
//    PDL: both key rows are staged to smem BEFORE the dependency sync, so
//    their DRAM latency overlaps the predecessor kernel's tail.
//    Block handles 2 pool rows; 8 warps split k; lane owns a batch pair.
//    grid = POOL/2 = 512, block = 256.
// ---------------------------------------------------------------------------
template <int STAGE>
__global__ __launch_bounds__(256) void sim_kernel(const float* __restrict__ keys)
{
    __shared__ float  skey[2][DIM];                    // 6 KB
    __shared__ float4 spart[8][32];
    __shared__ float2 snorm[8];

    int p0   = blockIdx.x * 2;
    int tid  = threadIdx.x;
    int warp = tid >> 5, lane = tid & 31;

    // ---- independent prefetch: key rows (keys are kernel inputs) ----
    {
        const float4* kr = (const float4*)(keys + (size_t)p0 * DIM);
#pragma unroll
        for (int i = tid; i < 2 * C4; i += 256) {
            ((float4*)skey)[i] = __ldg(kr + i);
        }
    }
    cudaGridDependencySynchronize();                   // vecT now valid
    __syncthreads();

    const float* vecT = STAGE ? g_residT : g_xnormT;   // [DIM][B]
    float*       simB = STAGE ? g_rsim   : g_sim;      // [B][POOL]
    const float2* xv  = (const float2*)vecT + lane;    // +k*(B/2)

    float a0x = 0.f, a0y = 0.f, a1x = 0.f, a1y = 0.f;
    float ss0 = 0.f, ss1 = 0.f;                        // identical across lanes
    int kb = warp * KSTRIPE;
#pragma unroll 8
    for (int i = 0; i < KSTRIPE; ++i) {
        int k = kb + i;
        float  kv0 = skey[0][k];
        float  kv1 = skey[1][k];
        ss0 += kv0 * kv0;
        ss1 += kv1 * kv1;
        float2 x = xv[(size_t)k * (B / 2)];
        a0x += kv0 * x.x; a0y += kv0 * x.y;
        a1x += kv1 * x.x; a1y += kv1 * x.y;
    }
    spart[warp][lane] = make_float4(a0x, a0y, a1x, a1y);
    if (lane == 0) snorm[warp] = make_float2(ss0, ss1);
    __syncthreads();
    if (warp == 0) {
        float sx = 0.f, sy = 0.f, tx = 0.f, ty = 0.f;
        float n0 = 0.f, n1 = 0.f;
#pragma unroll
        for (int w = 0; w < 8; ++w) {
            float4 v = spart[w][lane];
            sx += v.x; sy += v.y; tx += v.z; ty += v.w;
            n0 += snorm[w].x; n1 += snorm[w].y;
        }
        float i0 = rsqrtf(fmaxf(n0, 1e-12f));
        float i1 = rsqrtf(fmaxf(n1, 1e-12f));
        int b0 = lane * 2;
        simB[(size_t)b0 * POOL + p0]           = sx * i0;
        simB[(size_t)(b0 + 1) * POOL + p0]     = sy * i0;
        simB[(size_t)b0 * POOL + p0 + 1]       = tx * i1;
        simB[(size_t)(b0 + 1) * POOL + p0 + 1] = ty * i1;
    }
}

// ---------------------------------------------------------------------------
// 4) slim argmax over p (lowest index wins ties). One block per batch; one
//    float4 of the sim row per thread (coalesced 4KB). grid=B, block=256. PDL.
// ---------------------------------------------------------------------------
template <int STAGE>
__global__ __launch_bounds__(256) void argmax_kernel()
{
    cudaGridDependencySynchronize();
    __shared__ float swv[8];
    __shared__ int   swi[8];
    int b = blockIdx.x, tid = threadIdx.x;
    int warp = tid >> 5, lane = tid & 31;

    const float* simRow = (STAGE ? g_rsim : g_sim) + (size_t)b * POOL;
    float4 v4 = ((const float4*)simRow)[tid];

    // ascending p with strict > keeps lowest index on ties
    float best = v4.x; int bi = tid * 4;
    if (v4.y > best) { best = v4.y; bi = tid * 4 + 1; }
    if (v4.z > best) { best = v4.z; bi = tid * 4 + 2; }
    if (v4.w > best) { best = v4.w; bi = tid * 4 + 3; }

#pragma unroll
    for (int o = 16; o > 0; o >>= 1) {
        float vo = __shfl_down_sync(0xffffffffu, best, o);
        int   io = __shfl_down_sync(0xffffffffu, bi, o);
        if (vo > best || (vo == best && io < bi)) { best = vo; bi = io; }
    }
    if (lane == 0) { swv[warp] = best; swi[warp] = bi; }
    __syncthreads();
    if (tid == 0) {
        float v = swv[0]; int id = swi[0];
#pragma unroll
        for (int w = 1; w < 8; ++w) {
            if (swv[w] > v || (swv[w] == v && swi[w] < id)) {
                v = swv[w]; id = swi[w];
            }
        }
        if (STAGE) { g_idx2[b] = id; g_best2[b] = v; }
        else       { g_idx1[b] = id; g_best1[b] = v; }
    }
}

// ---------------------------------------------------------------------------
// 5) residT via 32x32 smem transpose: coalesced reads of pk rows AND
//    coalesced writes of residT. grid = 24*2 = 48, block = (32,32). PDL.
//    residT[c][b] = pk[idx1[b]][c] - xnormT[c][b]
// ---------------------------------------------------------------------------
__global__ void resid_kernel(const float* __restrict__ pk)
{
    cudaGridDependencySynchronize();
    __shared__ float tile[32][33];
    __shared__ int   sidx[32];
    int ct = blockIdx.x % (DIM / 32);     // 0..23
    int bt = blockIdx.x / (DIM / 32);     // 0..1
    int c0 = ct * 32, b0 = bt * 32;
    int tx = threadIdx.x, ty = threadIdx.y;

    if (ty == 0) sidx[tx] = g_idx1[b0 + tx];
    __syncthreads();
    // read: row b = b0+ty, cols c0+tx (128B coalesced per warp)
    tile[ty][tx] = pk[(size_t)sidx[ty] * DIM + c0 + tx];
    __syncthreads();
    // write: c = c0+ty, b = b0+tx (128B coalesced per warp)
    g_residT[(c0 + ty) * B + b0 + tx] =
        tile[tx][ty] - g_xnormT[(c0 + ty) * B + b0 + tx];
}

// ---------------------------------------------------------------------------
// 6) finish: both gathers spread over 256 blocks + scalar in block 256. PDL.
//    which=0 -> residual_prompt[g_idx2] @ out rows [0,16)
//    which=1 -> prompt[g_idx1]          @ out rows [16,32)
// ---------------------------------------------------------------------------
__global__ __launch_bounds__(256) void finish_kernel(
    const float4* __restrict__ prompt4,
    const float4* __restrict__ rprompt4,
    float4* __restrict__ out4,
    float* __restrict__ out_scalar,
    int write_scalar)
{
    cudaGridDependencySynchronize();
    if (blockIdx.x == 4 * B) {
        __shared__ float sh[2];
        if (write_scalar && threadIdx.x < 64) {
            float v = g_best1[threadIdx.x] + g_best2[threadIdx.x];
#pragma unroll
            for (int o = 16; o > 0; o >>= 1)
                v += __shfl_down_sync(0xffffffffu, v, o);
            if ((threadIdx.x & 31) == 0) sh[threadIdx.x >> 5] = v;
        }
        __syncthreads();
        if (write_scalar && threadIdx.x == 0)
            out_scalar[SCALAR_OFF] = (sh[0] + sh[1]) * (1.0f / (float)B);
        return;
    }
    int b     = blockIdx.x >> 2;
    int which = (blockIdx.x >> 1) & 1;
    int half  = blockIdx.x & 1;
    int idx = which ? g_idx1[b] : g_idx2[b];
    const int HQ = (LEN / 2) * C4;                   // 1536 float4 per half
    const float4* src = (which ? prompt4 : rprompt4)
                        + (size_t)idx * LEN * C4 + (size_t)half * HQ;
    float4* dst = out4 + ((size_t)b * NOUT + (which ? LEN : 0)
                          + (size_t)half * (LEN / 2)) * C4;
#pragma unroll
    for (int i = 0; i < HQ / 256; ++i)
        dst[threadIdx.x + i * 256] = src[threadIdx.x + i * 256];
}

// ---------------------------------------------------------------------------
// PDL launch helper
// ---------------------------------------------------------------------------
template <typename K, typename... Args>
static void launch_pdl(dim3 grid, dim3 block, K kernel, Args... args)
{
    cudaLaunchConfig_t cfg = {};
    cfg.gridDim = grid;
    cfg.blockDim = block;
    cfg.dynamicSmemBytes = 0;
    cfg.stream = 0;                      // legacy default (capture) stream
    cudaLaunchAttribute attr[1];
    attr[0].id = cudaLaunchAttributeProgrammaticStreamSerialization;
    attr[0].val.programmaticStreamSerializationAllowed = 1;
    cfg.attrs = attr;
    cfg.numAttrs = 1;
    cudaLaunchKernelEx(&cfg, kernel, args...);
}

// ---------------------------------------------------------------------------
// launch
// ---------------------------------------------------------------------------
extern "C" void kernel_launch(void* const* d_in, const int* in_sizes, int n_in,
                              void* d_out, int out_size)
{
    // Map inputs by element count (order-robust).
    const float* x_embed = nullptr;
    const float* prompt = nullptr, * rprompt = nullptr;
    const float* pkey = nullptr, * rpkey = nullptr;
    for (int i = 0; i < n_in; ++i) {
        int sz = in_sizes[i];
        if (sz == B * N * DIM) x_embed = (const float*)d_in[i];
        else if (sz == POOL * LEN * DIM) {
            if (!prompt) prompt = (const float*)d_in[i];
            else if (!rprompt) rprompt = (const float*)d_in[i];
        } else if (sz == POOL * DIM) {
            if (!pkey) pkey = (const float*)d_in[i];
            else if (!rpkey) rpkey = (const float*)d_in[i];
        }
    }
    float* out = (float*)d_out;

    copy_mean_kernel<<<B * NCHUNK, C4>>>((const float4*)x_embed, (float4*)out);
    launch_pdl(dim3(B), dim3(256), xnorm_kernel);
    launch_pdl(dim3(POOL / 2), dim3(256), sim_kernel<0>, pkey);
    launch_pdl(dim3(B), dim3(256), argmax_kernel<0>);
    launch_pdl(dim3(2 * DIM / 32), dim3(32, 32), resid_kernel, pkey);
    launch_pdl(dim3(POOL / 2), dim3(256), sim_kernel<1>, rpkey);
    launch_pdl(dim3(B), dim3(256), argmax_kernel<1>);
    int write_scalar = ((size_t)out_size > SCALAR_OFF) ? 1 : 0;
    launch_pdl(dim3(4 * B + 1), dim3(256), finish_kernel,
               (const float4*)prompt, (const float4*)rprompt, (float4*)out,
               out, write_scalar);
}